// round 9
// baseline (speedup 1.0000x reference)
#include <cuda_runtime.h>
#include <cuda_fp16.h>

#define BB   32      // batch
#define NN   2048    // input capsules
#define IL   32      // input capsule length
#define CC   32      // output capsules
#define LL   32      // output capsule length
#define KK   1024    // CC*LL
#define NCH1 128     // j-chunks for u/s0 kernel (16 j each)
#define PCH  32      // pass CTAs per b (each CTA covers 64 j)

typedef unsigned long long ull;

// Scratch (device globals: allocation-free rule)
__device__ __half g_uh [(size_t)BB * NN * KK];    // 128 MB prediction tensor (fp16)
__device__ float  g_s0p[(size_t)BB * NCH1 * KK];  // s partials, round 0 (16 MB)
__device__ float  g_sp [(size_t)BB * PCH * KK];   // s partials, rounds 1/2 (4 MB)
__device__ float  g_v0 [BB * KK];
__device__ float  g_v1 [BB * KK];
__device__ float  g_dummy[1];

__device__ __forceinline__ void ffma2(ull& acc, ull a, ull b) {
    asm("fma.rn.f32x2 %0, %1, %2, %0;" : "+l"(acc) : "l"(a), "l"(b));
}
__device__ __forceinline__ void fadd2(ull& acc, ull a) {
    asm("add.rn.f32x2 %0, %1, %0;" : "+l"(acc) : "l"(a));
}
__device__ __forceinline__ float2 up2(ull v) {
    float2 f;
    asm("mov.b64 {%0, %1}, %2;" : "=f"(f.x), "=f"(f.y) : "l"(v));
    return f;
}
__device__ __forceinline__ __half2 geth2(const uint4& v, int p) {
    unsigned u = (&v.x)[p];
    return *reinterpret_cast<const __half2*>(&u);
}

__global__ void k_dummy(float* p) { if (threadIdx.x == 0) p[0] = 0.f; }

// K1 v6: u[b,j,k] = sum_i x[b,j,i]*W[j,i,k]; s0 partial = sum_j u / 32.
// CTA = (16-j chunk, 256-k quarter). Thread: kg=tid&63 owns 4 k (2 f32x2
// k-pairs), bg=tid>>6 owns 8 b. acc layout (k-pair, b) makes BOTH FFMA2
// operands direct smem loads: W k-pairs via ulonglong2 from the cp.async
// ring (no splat movs), x via duplicated-float2 smem (no pack movs).
// Per i-pair: 2 + 8 LDS.128 + 32 FFMA2 = 42 issues / 64 fma-cycles ->
// fma-pipe-bound. 3-stage cp.async ring = ~1000 cyc of DRAM-latency cover.
__global__ void __launch_bounds__(256, 2)
k1(const float* __restrict__ x, const float* __restrict__ Wt) {
    const int kg    = threadIdx.x & 63;    // 4 k each
    const int bg    = threadIdx.x >> 6;    // 4 groups x 8 b
    const int chunk = blockIdx.x;          // 0..127
    const int kq    = blockIdx.y;          // 0..3
    const int j0g   = chunk * 16;

    __shared__ __align__(16) float  wbuf[3][8][256];  // 24 KB W ring
    __shared__ __align__(16) float2 xs2[2][32][32];   // 16 KB x duplicated

    // cp.async mapping: 8 rows x 32 threads x 32 B
    const int wr = threadIdx.x >> 5;
    const int wl = threadIdx.x & 31;

    auto issue_stage = [&](int g) {
        const int jg = j0g + (g >> 2);
        const int ibase = (g & 3) * 8;
        const float* src = Wt + (size_t)jg * (IL * KK) + (size_t)(ibase + wr) * KK
                         + kq * 256 + wl * 8;
        unsigned dst = (unsigned)__cvta_generic_to_shared(&wbuf[g % 3][wr][wl * 8]);
        asm volatile(
            "cp.async.cg.shared.global [%0], [%1], 16;\n\t"
            "cp.async.cg.shared.global [%2], [%3], 16;"
            :: "r"(dst), "l"(src), "r"(dst + 16), "l"(src + 4) : "memory");
    };

    ull acc[2][8], s0[2][8];               // [k-pair][b] f32x2
#pragma unroll
    for (int kp = 0; kp < 2; kp++)
#pragma unroll
        for (int bb = 0; bb < 8; bb++) { acc[kp][bb] = 0ull; s0[kp][bb] = 0ull; }

    issue_stage(0);
    asm volatile("cp.async.commit_group;" ::: "memory");
    issue_stage(1);
    asm volatile("cp.async.commit_group;" ::: "memory");

    for (int g = 0; g < 64; g++) {         // 64 stages: 16 j x 4 i-blocks of 8
        asm volatile("cp.async.wait_group 1;" ::: "memory");
        __syncthreads();

        if ((g & 7) == 0) {
            // stage x duplicated for the next 2 j
            const int jp = j0g + (g >> 2);
#pragma unroll
            for (int r = 0; r < 8; r++) {
                int idx = threadIdx.x + 256 * r;
                int jl = idx >> 10, rem = idx & 1023;
                int b = rem >> 5, i = rem & 31;
                float v = x[((size_t)b * NN + jp + jl) * IL + i];
                xs2[jl][b][i] = make_float2(v, v);
            }
            __syncthreads();
        }

        // compute stage g (8 i-rows = 4 i-pairs)
        const int jl = (g >> 2) & 1;
        const int ib = (g & 3) * 8;
        const float (*wb)[256] = wbuf[g % 3];
#pragma unroll
        for (int ip = 0; ip < 4; ip++) {
            const int i = ib + ip * 2;
            // W k-pairs: (k0k1, k2k3) for i and i+1 — direct ull operands
            ulonglong2 w0 = *reinterpret_cast<const ulonglong2*>(&wb[ip * 2][kg * 4]);
            ulonglong2 w1 = *reinterpret_cast<const ulonglong2*>(&wb[ip * 2 + 1][kg * 4]);
#pragma unroll
            for (int bb = 0; bb < 8; bb++) {
                // (x_i dup, x_{i+1} dup) in one LDS.128 (warp-broadcast)
                ulonglong2 xx =
                    *reinterpret_cast<const ulonglong2*>(&xs2[jl][bg * 8 + bb][i]);
                ffma2(acc[0][bb], w0.x, xx.x);
                ffma2(acc[1][bb], w0.y, xx.x);
                ffma2(acc[0][bb], w1.x, xx.y);
                ffma2(acc[1][bb], w1.y, xx.y);
            }
        }

        if ((g & 3) == 3) {
            // j complete: store u row (fp16), fold s0, reset acc
            const int jg = j0g + (g >> 2);
            const size_t kb = (size_t)kq * 256 + (size_t)kg * 4;
#pragma unroll
            for (int bb = 0; bb < 8; bb++) {
                const int b = bg * 8 + bb;
                float2 f0 = up2(acc[0][bb]);   // (k0, k1)
                float2 f1 = up2(acc[1][bb]);   // (k2, k3)
                __half2 h0 = __floats2half2_rn(f0.x, f0.y);
                __half2 h1 = __floats2half2_rn(f1.x, f1.y);
                uint2 pk;
                pk.x = *reinterpret_cast<unsigned*>(&h0);
                pk.y = *reinterpret_cast<unsigned*>(&h1);
                *reinterpret_cast<uint2*>(g_uh + ((size_t)b * NN + jg) * KK + kb) = pk;
                fadd2(s0[0][bb], acc[0][bb]);
                fadd2(s0[1][bb], acc[1][bb]);
                acc[0][bb] = 0ull;
                acc[1][bb] = 0ull;
            }
        }

        if (g + 2 < 64) issue_stage(g + 2);
        asm volatile("cp.async.commit_group;" ::: "memory");
    }

    // s0 partial store (softmax(0) coupling = 1/32)
    const float scl = 1.0f / 32.0f;
    const size_t kb = (size_t)kq * 256 + (size_t)kg * 4;
#pragma unroll
    for (int bb = 0; bb < 8; bb++) {
        const int b = bg * 8 + bb;
        float2 f0 = up2(s0[0][bb]);
        float2 f1 = up2(s0[1][bb]);
        *reinterpret_cast<float4*>(g_s0p + ((size_t)b * NCH1 + chunk) * KK + kb) =
            make_float4(f0.x * scl, f0.y * scl, f1.x * scl, f1.y * scl);
    }
}

// Routing pass v4 (measured ~28us each). Lane t's uint4 group q (index
// t+32q of the u row) covers k = 8t+256q+e (e<8), all in capsule
// c_q = (t>>2)+8q. Quad shfl completes each logit; shfl xor 4/8/16 spans
// the 32 capsules for the softmax. v as fp16x2 registers; u raw, converted
// on the fly. Two rows per body, interleaved softmax chains.
template <int NP>
__global__ void __launch_bounds__(256, 2)
k_pass(const float* __restrict__ vin0, const float* __restrict__ vin1,
       float* __restrict__ sp) {
    const int b = blockIdx.y;
    const int w = threadIdx.x >> 5;
    const int t = threadIdx.x & 31;

    __shared__ float red[8][1032];     // CTA reduction (16B-aligned rows)

    // v as half2 registers at the u k-mapping (NP==2 folds v0+v1)
    __half2 vh[16];
#pragma unroll
    for (int q = 0; q < 4; q++) {
        float4 a = *reinterpret_cast<const float4*>(vin0 + (size_t)b * KK + 8 * t + 256 * q);
        float4 c4 = *reinterpret_cast<const float4*>(vin0 + (size_t)b * KK + 8 * t + 256 * q + 4);
        if (NP == 2) {
            float4 a1 = *reinterpret_cast<const float4*>(vin1 + (size_t)b * KK + 8 * t + 256 * q);
            float4 c1 = *reinterpret_cast<const float4*>(vin1 + (size_t)b * KK + 8 * t + 256 * q + 4);
            a.x += a1.x; a.y += a1.y; a.z += a1.z; a.w += a1.w;
            c4.x += c1.x; c4.y += c1.y; c4.z += c1.z; c4.w += c1.w;
        }
        vh[q * 4 + 0] = __floats2half2_rn(a.x, a.y);
        vh[q * 4 + 1] = __floats2half2_rn(a.z, a.w);
        vh[q * 4 + 2] = __floats2half2_rn(c4.x, c4.y);
        vh[q * 4 + 3] = __floats2half2_rn(c4.z, c4.w);
    }

    float sacc[32];
#pragma unroll
    for (int l = 0; l < 32; l++) sacc[l] = 0.f;

    const int jbase = blockIdx.x * 64 + w * 8;   // 8 warps x 8 j = 64 j / CTA
    const uint4* up = reinterpret_cast<const uint4*>(g_uh + ((size_t)b * NN + jbase) * KK);

    uint4 raw0[4], raw1[4];
#pragma unroll
    for (int q = 0; q < 4; q++) raw0[q] = up[q * 32 + t];          // j0
#pragma unroll
    for (int q = 0; q < 4; q++) raw1[q] = up[128 + q * 32 + t];    // j1

    for (int jb = 0; jb < 8; jb += 2) {
        // free raw0 early: copy, then prefetch j+2 into it
        uint4 cpy0[4];
#pragma unroll
        for (int q = 0; q < 4; q++) cpy0[q] = raw0[q];
        if (jb + 2 < 8) {
#pragma unroll
            for (int q = 0; q < 4; q++) raw0[q] = up[(jb + 2) * 128 + q * 32 + t];
        }

        // logits for both rows (HFMA2 dot), interleaved
        float d0[4], d1[4];
#pragma unroll
        for (int q = 0; q < 4; q++) {
            __half2 a0 = __float2half2_rn(0.f), a1 = __float2half2_rn(0.f);
#pragma unroll
            for (int p = 0; p < 4; p++) {
                a0 = __hfma2(geth2(cpy0[q], p), vh[q * 4 + p], a0);
                a1 = __hfma2(geth2(raw1[q], p), vh[q * 4 + p], a1);
            }
            float2 f0 = __half22float2(a0), f1 = __half22float2(a1);
            d0[q] = f0.x + f0.y;
            d1[q] = f1.x + f1.y;
            d0[q] += __shfl_xor_sync(0xffffffffu, d0[q], 1);
            d1[q] += __shfl_xor_sync(0xffffffffu, d1[q], 1);
            d0[q] += __shfl_xor_sync(0xffffffffu, d0[q], 2);
            d1[q] += __shfl_xor_sync(0xffffffffu, d1[q], 2);
        }

        // softmax over 32 capsules, two independent chains interleaved
        float m0 = fmaxf(fmaxf(d0[0], d0[1]), fmaxf(d0[2], d0[3]));
        float m1 = fmaxf(fmaxf(d1[0], d1[1]), fmaxf(d1[2], d1[3]));
        m0 = fmaxf(m0, __shfl_xor_sync(0xffffffffu, m0, 4));
        m1 = fmaxf(m1, __shfl_xor_sync(0xffffffffu, m1, 4));
        m0 = fmaxf(m0, __shfl_xor_sync(0xffffffffu, m0, 8));
        m1 = fmaxf(m1, __shfl_xor_sync(0xffffffffu, m1, 8));
        m0 = fmaxf(m0, __shfl_xor_sync(0xffffffffu, m0, 16));
        m1 = fmaxf(m1, __shfl_xor_sync(0xffffffffu, m1, 16));

        float ce0[4], ce1[4];
#pragma unroll
        for (int q = 0; q < 4; q++) {
            ce0[q] = __expf(d0[q] - m0);
            ce1[q] = __expf(d1[q] - m1);
        }
        float Z0 = (ce0[0] + ce0[1]) + (ce0[2] + ce0[3]);
        float Z1 = (ce1[0] + ce1[1]) + (ce1[2] + ce1[3]);
        Z0 += __shfl_xor_sync(0xffffffffu, Z0, 4);
        Z1 += __shfl_xor_sync(0xffffffffu, Z1, 4);
        Z0 += __shfl_xor_sync(0xffffffffu, Z0, 8);
        Z1 += __shfl_xor_sync(0xffffffffu, Z1, 8);
        Z0 += __shfl_xor_sync(0xffffffffu, Z0, 16);
        Z1 += __shfl_xor_sync(0xffffffffu, Z1, 16);
        const float i0 = __fdividef(1.0f, Z0);
        const float i1 = __fdividef(1.0f, Z1);

        // accumulate both rows (cvt on the fly)
#pragma unroll
        for (int q = 0; q < 4; q++) {
            const float c0 = ce0[q] * i0;
            const float c1 = ce1[q] * i1;
#pragma unroll
            for (int p = 0; p < 4; p++) {
                float2 f = __half22float2(geth2(cpy0[q], p));
                sacc[8 * q + 2 * p]     += c0 * f.x;
                sacc[8 * q + 2 * p + 1] += c0 * f.y;
                f = __half22float2(geth2(raw1[q], p));
                sacc[8 * q + 2 * p]     += c1 * f.x;
                sacc[8 * q + 2 * p + 1] += c1 * f.y;
            }
        }

        // raw1 now free: prefetch j+3
        if (jb + 3 < 8) {
#pragma unroll
            for (int q = 0; q < 4; q++) raw1[q] = up[(jb + 3) * 128 + q * 32 + t];
        }
    }

    // CTA reduction across the 8 warps (natural k layout)
#pragma unroll
    for (int q = 0; q < 4; q++) {
        *reinterpret_cast<float4*>(&red[w][8 * t + 256 * q])     =
            make_float4(sacc[8 * q + 0], sacc[8 * q + 1], sacc[8 * q + 2], sacc[8 * q + 3]);
        *reinterpret_cast<float4*>(&red[w][8 * t + 256 * q + 4]) =
            make_float4(sacc[8 * q + 4], sacc[8 * q + 5], sacc[8 * q + 6], sacc[8 * q + 7]);
    }
    __syncthreads();

    float4 s = make_float4(0.f, 0.f, 0.f, 0.f);
#pragma unroll
    for (int ww = 0; ww < 8; ww++) {
        float4 p = *reinterpret_cast<const float4*>(&red[ww][4 * threadIdx.x]);
        s.x += p.x; s.y += p.y; s.z += p.z; s.w += p.w;
    }
    *reinterpret_cast<float4*>(sp + ((size_t)b * PCH + blockIdx.x) * KK + 4 * threadIdx.x) = s;
}

// Finalize: reduce NCH chunk partials + biases, squash -> v.
// One CTA (8 warps) per (b,c) for memory-level parallelism on the reduction.
template <int NCH>
__global__ void __launch_bounds__(256)
k_fin(const float* __restrict__ sp, const float* __restrict__ biases,
      float* __restrict__ vout) {
    const int bc = blockIdx.x;
    const int b = bc >> 5, c = bc & 31;
    const int w = threadIdx.x >> 5, lane = threadIdx.x & 31;

    float s = 0.f;
    const float* p = sp + (size_t)b * NCH * KK + c * LL + lane;
#pragma unroll 8
    for (int n = w; n < NCH; n += 8) s += p[(size_t)n * KK];

    __shared__ float red[8][32];
    red[w][lane] = s;
    __syncthreads();

    if (w == 0) {
        float v = biases[c * LL + lane];
#pragma unroll
        for (int ww = 0; ww < 8; ww++) v += red[ww][lane];
        float n2 = v * v;
#pragma unroll
        for (int o = 16; o; o >>= 1) n2 += __shfl_xor_sync(0xffffffffu, n2, o);
        const float nn = sqrtf(n2);
        const float f = n2 / (1.0f + n2) / (nn + 1e-7f);   // squash factor
        vout[(size_t)b * KK + c * LL + lane] = f * v;
    }
}

extern "C" void kernel_launch(void* const* d_in, const int* in_sizes, int n_in,
                              void* d_out, int out_size) {
    const float* x      = (const float*)d_in[0];  // [32,8,8,32,32] = [B,N,iL]
    const float* Wt     = (const float*)d_in[1];  // [2048,32,1024]
    const float* biases = (const float*)d_in[2];  // [32,32]
    float* out = (float*)d_out;                   // [32,32,32]

    float *s0p, *sp, *v0, *v1, *dm;
    cudaGetSymbolAddress((void**)&s0p, g_s0p);
    cudaGetSymbolAddress((void**)&sp,  g_sp);
    cudaGetSymbolAddress((void**)&v0,  g_v0);
    cudaGetSymbolAddress((void**)&v1,  g_v1);
    cudaGetSymbolAddress((void**)&dm,  g_dummy);

    // 3 dummies keep k1 in the ncu-profiled slot.
    k_dummy<<<1, 32>>>(dm);                              // 0
    k_dummy<<<1, 32>>>(dm);                              // 1
    k_dummy<<<1, 32>>>(dm);                              // 2
    k1<<<dim3(NCH1, 4), 256>>>(x, Wt);                   // 3 <- profiled
    k_fin<NCH1><<<BB * CC, 256>>>(s0p, biases, v0);      // 4
    k_pass<1><<<dim3(PCH, BB), 256>>>(v0, v0, sp);       // 5
    k_fin<PCH><<<BB * CC, 256>>>(sp, biases, v1);        // 6
    k_pass<2><<<dim3(PCH, BB), 256>>>(v0, v1, sp);       // 7
    k_fin<PCH><<<BB * CC, 256>>>(sp, biases, out);       // 8
}

// round 10
// speedup vs baseline: 1.1606x; 1.1606x over previous
#include <cuda_runtime.h>
#include <cuda_fp16.h>

#define BB   32      // batch
#define NN   2048    // input capsules
#define IL   32      // input capsule length
#define CC   32      // output capsules
#define LL   32      // output capsule length
#define KK   1024    // CC*LL
#define NCH1 128     // j-chunks for u/s0 kernel (16 j each)
#define PCH  32      // pass CTAs per b (each CTA covers 64 j)

typedef unsigned long long ull;

// Scratch (device globals: allocation-free rule)
__device__ __half g_uh [(size_t)BB * NN * KK];    // 128 MB prediction tensor (fp16)
__device__ float  g_s0p[(size_t)BB * NCH1 * KK];  // s partials, round 0 (16 MB)
__device__ float  g_sp [(size_t)BB * PCH * KK];   // s partials, rounds 1/2 (4 MB)
__device__ float  g_v0 [BB * KK];
__device__ float  g_v1 [BB * KK];
__device__ float  g_dummy[1];

__device__ __forceinline__ void ffma2(ull& acc, ull a, ull b) {
    asm("fma.rn.f32x2 %0, %1, %2, %0;" : "+l"(acc) : "l"(a), "l"(b));
}
__device__ __forceinline__ void fadd2(ull& acc, ull a) {
    asm("add.rn.f32x2 %0, %1, %0;" : "+l"(acc) : "l"(a));
}
__device__ __forceinline__ float2 up2(ull v) {
    float2 f;
    asm("mov.b64 {%0, %1}, %2;" : "=f"(f.x), "=f"(f.y) : "l"(v));
    return f;
}
__device__ __forceinline__ ull splat(float v) {
    ull r;
    asm("mov.b64 %0, {%1, %1};" : "=l"(r) : "f"(v));
    return r;
}
__device__ __forceinline__ ull pack2(float a, float b) {
    ull r;
    asm("mov.b64 %0, {%1, %2};" : "=l"(r) : "f"(a), "f"(b));
    return r;
}
__device__ __forceinline__ __half2 geth2(const uint4& v, int p) {
    unsigned u = (&v.x)[p];
    return *reinterpret_cast<const __half2*>(&u);
}

__global__ void k_dummy(float* p) { if (threadIdx.x == 0) p[0] = 0.f; }

// K1 v7 = v5 core (best measured: 131us) + DEEP cp.async ring.
// v5 was DRAM-throughput-limited at its achieved 3.1 TB/s because only
// 2 stages (32 KB/SM) were in flight. 5-stage ring with depth-4 prefetch
// doubles outstanding bytes (64 KB/SM) to approach the ~6.3 TB/s LTS cap.
// Thread: kg=tid&63 owns 4 k, bg=tid>>6 owns 8 b (4 f32x2 b-pairs).
// x staged transposed so b-pair f32x2 operands come from one LDS.128;
// W scalars splat once per i on the alu pipe.
__global__ void __launch_bounds__(256, 2)
k1(const float* __restrict__ x, const float* __restrict__ Wt) {
    const int kg    = threadIdx.x & 63;    // 4 k each
    const int bg    = threadIdx.x >> 6;    // 4 groups x 8 b
    const int chunk = blockIdx.x;          // 0..127
    const int kq    = blockIdx.y;          // 0..3
    const int j0g   = chunk * 16;

    __shared__ __align__(16) float wbuf[5][8][256];   // 40 KB W ring
    __shared__ __align__(16) float xs[2][32][36];     // 9 KB x (transposed, padded)

    // cp.async mapping: 8 rows x 32 threads x 32 B
    const int wr = threadIdx.x >> 5;
    const int wl = threadIdx.x & 31;

    auto issue_stage = [&](int g) {
        const int jg = j0g + (g >> 2);
        const int ibase = (g & 3) * 8;
        const float* src = Wt + (size_t)jg * (IL * KK) + (size_t)(ibase + wr) * KK
                         + kq * 256 + wl * 8;
        unsigned dst = (unsigned)__cvta_generic_to_shared(&wbuf[g % 5][wr][wl * 8]);
        asm volatile(
            "cp.async.cg.shared.global [%0], [%1], 16;\n\t"
            "cp.async.cg.shared.global [%2], [%3], 16;"
            :: "r"(dst), "l"(src), "r"(dst + 16), "l"(src + 4) : "memory");
    };

    ull acc[4][4], s0[4][4];               // [k][b-pair] f32x2
#pragma unroll
    for (int k = 0; k < 4; k++)
#pragma unroll
        for (int bp = 0; bp < 4; bp++) { acc[k][bp] = 0ull; s0[k][bp] = 0ull; }

    // prologue: 4 stages in flight
#pragma unroll
    for (int pg = 0; pg < 4; pg++) {
        issue_stage(pg);
        asm volatile("cp.async.commit_group;" ::: "memory");
    }

    for (int g = 0; g < 64; g++) {         // 64 stages: 16 j x 4 i-blocks of 8
        asm volatile("cp.async.wait_group 3;" ::: "memory");
        __syncthreads();

        if ((g & 7) == 0) {
            // stage x for j-pair (transposed, pad 36 for aligned LDS.128)
            const int jp = j0g + (g >> 2);
#pragma unroll
            for (int r = 0; r < 8; r++) {
                int idx = threadIdx.x + 256 * r;
                int jl = idx >> 10, rem = idx & 1023;
                int b = rem >> 5, i = rem & 31;
                xs[jl][i][b] = x[((size_t)b * NN + jp + jl) * IL + i];
            }
            __syncthreads();
        }

        // compute stage g (8 i-rows)
        const int jl = (g >> 2) & 1;
        const int ib = (g & 3) * 8;
        const float (*wb)[256] = wbuf[g % 5];
#pragma unroll
        for (int ii = 0; ii < 8; ii++) {
            float4 w = *reinterpret_cast<const float4*>(&wb[ii][kg * 4]);
            ull ws0 = splat(w.x), ws1 = splat(w.y), ws2 = splat(w.z), ws3 = splat(w.w);
            float4 xa = *reinterpret_cast<const float4*>(&xs[jl][ib + ii][bg * 8]);
            float4 xb = *reinterpret_cast<const float4*>(&xs[jl][ib + ii][bg * 8 + 4]);
            ull xp0 = pack2(xa.x, xa.y), xp1 = pack2(xa.z, xa.w);
            ull xp2 = pack2(xb.x, xb.y), xp3 = pack2(xb.z, xb.w);
            ffma2(acc[0][0], ws0, xp0); ffma2(acc[0][1], ws0, xp1);
            ffma2(acc[0][2], ws0, xp2); ffma2(acc[0][3], ws0, xp3);
            ffma2(acc[1][0], ws1, xp0); ffma2(acc[1][1], ws1, xp1);
            ffma2(acc[1][2], ws1, xp2); ffma2(acc[1][3], ws1, xp3);
            ffma2(acc[2][0], ws2, xp0); ffma2(acc[2][1], ws2, xp1);
            ffma2(acc[2][2], ws2, xp2); ffma2(acc[2][3], ws2, xp3);
            ffma2(acc[3][0], ws3, xp0); ffma2(acc[3][1], ws3, xp1);
            ffma2(acc[3][2], ws3, xp2); ffma2(acc[3][3], ws3, xp3);
        }

        if ((g & 3) == 3) {
            // j complete: store u row (fp16), fold s0, reset acc
            const int jg = j0g + (g >> 2);
            const size_t kb = (size_t)kq * 256 + (size_t)kg * 4;
#pragma unroll
            for (int bp = 0; bp < 4; bp++) {
                float2 f0 = up2(acc[0][bp]), f1 = up2(acc[1][bp]);
                float2 f2 = up2(acc[2][bp]), f3 = up2(acc[3][bp]);
                const int be = bg * 8 + bp * 2;
                __half2 h0 = __floats2half2_rn(f0.x, f1.x);
                __half2 h1 = __floats2half2_rn(f2.x, f3.x);
                uint2 pk;
                pk.x = *reinterpret_cast<unsigned*>(&h0);
                pk.y = *reinterpret_cast<unsigned*>(&h1);
                *reinterpret_cast<uint2*>(g_uh + ((size_t)be * NN + jg) * KK + kb) = pk;
                h0 = __floats2half2_rn(f0.y, f1.y);
                h1 = __floats2half2_rn(f2.y, f3.y);
                pk.x = *reinterpret_cast<unsigned*>(&h0);
                pk.y = *reinterpret_cast<unsigned*>(&h1);
                *reinterpret_cast<uint2*>(g_uh + ((size_t)(be + 1) * NN + jg) * KK + kb) = pk;
#pragma unroll
                for (int k = 0; k < 4; k++) {
                    fadd2(s0[k][bp], acc[k][bp]);
                    acc[k][bp] = 0ull;
                }
            }
        }

        if (g + 4 < 64) issue_stage(g + 4);
        asm volatile("cp.async.commit_group;" ::: "memory");
    }

    // s0 partial store (softmax(0) coupling = 1/32)
    const float scl = 1.0f / 32.0f;
    const size_t kb = (size_t)kq * 256 + (size_t)kg * 4;
#pragma unroll
    for (int bp = 0; bp < 4; bp++) {
        float2 f0 = up2(s0[0][bp]), f1 = up2(s0[1][bp]);
        float2 f2 = up2(s0[2][bp]), f3 = up2(s0[3][bp]);
        const int be = bg * 8 + bp * 2;
        *reinterpret_cast<float4*>(g_s0p + ((size_t)be * NCH1 + chunk) * KK + kb) =
            make_float4(f0.x * scl, f1.x * scl, f2.x * scl, f3.x * scl);
        *reinterpret_cast<float4*>(g_s0p + ((size_t)(be + 1) * NCH1 + chunk) * KK + kb) =
            make_float4(f0.y * scl, f1.y * scl, f2.y * scl, f3.y * scl);
    }
}

// Routing pass v4 (measured ~28us each). Lane t's uint4 group q (index
// t+32q of the u row) covers k = 8t+256q+e (e<8), all in capsule
// c_q = (t>>2)+8q. Quad shfl completes each logit; shfl xor 4/8/16 spans
// the 32 capsules for the softmax. v as fp16x2 registers; u raw, converted
// on the fly. Two rows per body, interleaved softmax chains.
template <int NP>
__global__ void __launch_bounds__(256, 2)
k_pass(const float* __restrict__ vin0, const float* __restrict__ vin1,
       float* __restrict__ sp) {
    const int b = blockIdx.y;
    const int w = threadIdx.x >> 5;
    const int t = threadIdx.x & 31;

    __shared__ float red[8][1032];     // CTA reduction (16B-aligned rows)

    // v as half2 registers at the u k-mapping (NP==2 folds v0+v1)
    __half2 vh[16];
#pragma unroll
    for (int q = 0; q < 4; q++) {
        float4 a = *reinterpret_cast<const float4*>(vin0 + (size_t)b * KK + 8 * t + 256 * q);
        float4 c4 = *reinterpret_cast<const float4*>(vin0 + (size_t)b * KK + 8 * t + 256 * q + 4);
        if (NP == 2) {
            float4 a1 = *reinterpret_cast<const float4*>(vin1 + (size_t)b * KK + 8 * t + 256 * q);
            float4 c1 = *reinterpret_cast<const float4*>(vin1 + (size_t)b * KK + 8 * t + 256 * q + 4);
            a.x += a1.x; a.y += a1.y; a.z += a1.z; a.w += a1.w;
            c4.x += c1.x; c4.y += c1.y; c4.z += c1.z; c4.w += c1.w;
        }
        vh[q * 4 + 0] = __floats2half2_rn(a.x, a.y);
        vh[q * 4 + 1] = __floats2half2_rn(a.z, a.w);
        vh[q * 4 + 2] = __floats2half2_rn(c4.x, c4.y);
        vh[q * 4 + 3] = __floats2half2_rn(c4.z, c4.w);
    }

    float sacc[32];
#pragma unroll
    for (int l = 0; l < 32; l++) sacc[l] = 0.f;

    const int jbase = blockIdx.x * 64 + w * 8;   // 8 warps x 8 j = 64 j / CTA
    const uint4* up = reinterpret_cast<const uint4*>(g_uh + ((size_t)b * NN + jbase) * KK);

    uint4 raw0[4], raw1[4];
#pragma unroll
    for (int q = 0; q < 4; q++) raw0[q] = up[q * 32 + t];          // j0
#pragma unroll
    for (int q = 0; q < 4; q++) raw1[q] = up[128 + q * 32 + t];    // j1

    for (int jb = 0; jb < 8; jb += 2) {
        // free raw0 early: copy, then prefetch j+2 into it
        uint4 cpy0[4];
#pragma unroll
        for (int q = 0; q < 4; q++) cpy0[q] = raw0[q];
        if (jb + 2 < 8) {
#pragma unroll
            for (int q = 0; q < 4; q++) raw0[q] = up[(jb + 2) * 128 + q * 32 + t];
        }

        // logits for both rows (HFMA2 dot), interleaved
        float d0[4], d1[4];
#pragma unroll
        for (int q = 0; q < 4; q++) {
            __half2 a0 = __float2half2_rn(0.f), a1 = __float2half2_rn(0.f);
#pragma unroll
            for (int p = 0; p < 4; p++) {
                a0 = __hfma2(geth2(cpy0[q], p), vh[q * 4 + p], a0);
                a1 = __hfma2(geth2(raw1[q], p), vh[q * 4 + p], a1);
            }
            float2 f0 = __half22float2(a0), f1 = __half22float2(a1);
            d0[q] = f0.x + f0.y;
            d1[q] = f1.x + f1.y;
            d0[q] += __shfl_xor_sync(0xffffffffu, d0[q], 1);
            d1[q] += __shfl_xor_sync(0xffffffffu, d1[q], 1);
            d0[q] += __shfl_xor_sync(0xffffffffu, d0[q], 2);
            d1[q] += __shfl_xor_sync(0xffffffffu, d1[q], 2);
        }

        // softmax over 32 capsules, two independent chains interleaved
        float m0 = fmaxf(fmaxf(d0[0], d0[1]), fmaxf(d0[2], d0[3]));
        float m1 = fmaxf(fmaxf(d1[0], d1[1]), fmaxf(d1[2], d1[3]));
        m0 = fmaxf(m0, __shfl_xor_sync(0xffffffffu, m0, 4));
        m1 = fmaxf(m1, __shfl_xor_sync(0xffffffffu, m1, 4));
        m0 = fmaxf(m0, __shfl_xor_sync(0xffffffffu, m0, 8));
        m1 = fmaxf(m1, __shfl_xor_sync(0xffffffffu, m1, 8));
        m0 = fmaxf(m0, __shfl_xor_sync(0xffffffffu, m0, 16));
        m1 = fmaxf(m1, __shfl_xor_sync(0xffffffffu, m1, 16));

        float ce0[4], ce1[4];
#pragma unroll
        for (int q = 0; q < 4; q++) {
            ce0[q] = __expf(d0[q] - m0);
            ce1[q] = __expf(d1[q] - m1);
        }
        float Z0 = (ce0[0] + ce0[1]) + (ce0[2] + ce0[3]);
        float Z1 = (ce1[0] + ce1[1]) + (ce1[2] + ce1[3]);
        Z0 += __shfl_xor_sync(0xffffffffu, Z0, 4);
        Z1 += __shfl_xor_sync(0xffffffffu, Z1, 4);
        Z0 += __shfl_xor_sync(0xffffffffu, Z0, 8);
        Z1 += __shfl_xor_sync(0xffffffffu, Z1, 8);
        Z0 += __shfl_xor_sync(0xffffffffu, Z0, 16);
        Z1 += __shfl_xor_sync(0xffffffffu, Z1, 16);
        const float i0 = __fdividef(1.0f, Z0);
        const float i1 = __fdividef(1.0f, Z1);

        // accumulate both rows (cvt on the fly)
#pragma unroll
        for (int q = 0; q < 4; q++) {
            const float c0 = ce0[q] * i0;
            const float c1 = ce1[q] * i1;
#pragma unroll
            for (int p = 0; p < 4; p++) {
                float2 f = __half22float2(geth2(cpy0[q], p));
                sacc[8 * q + 2 * p]     += c0 * f.x;
                sacc[8 * q + 2 * p + 1] += c0 * f.y;
                f = __half22float2(geth2(raw1[q], p));
                sacc[8 * q + 2 * p]     += c1 * f.x;
                sacc[8 * q + 2 * p + 1] += c1 * f.y;
            }
        }

        // raw1 now free: prefetch j+3
        if (jb + 3 < 8) {
#pragma unroll
            for (int q = 0; q < 4; q++) raw1[q] = up[(jb + 3) * 128 + q * 32 + t];
        }
    }

    // CTA reduction across the 8 warps (natural k layout)
#pragma unroll
    for (int q = 0; q < 4; q++) {
        *reinterpret_cast<float4*>(&red[w][8 * t + 256 * q])     =
            make_float4(sacc[8 * q + 0], sacc[8 * q + 1], sacc[8 * q + 2], sacc[8 * q + 3]);
        *reinterpret_cast<float4*>(&red[w][8 * t + 256 * q + 4]) =
            make_float4(sacc[8 * q + 4], sacc[8 * q + 5], sacc[8 * q + 6], sacc[8 * q + 7]);
    }
    __syncthreads();

    float4 s = make_float4(0.f, 0.f, 0.f, 0.f);
#pragma unroll
    for (int ww = 0; ww < 8; ww++) {
        float4 p = *reinterpret_cast<const float4*>(&red[ww][4 * threadIdx.x]);
        s.x += p.x; s.y += p.y; s.z += p.z; s.w += p.w;
    }
    *reinterpret_cast<float4*>(sp + ((size_t)b * PCH + blockIdx.x) * KK + 4 * threadIdx.x) = s;
}

// Finalize: reduce NCH chunk partials + biases, squash -> v.
// One CTA (8 warps) per (b,c) for memory-level parallelism on the reduction.
template <int NCH>
__global__ void __launch_bounds__(256)
k_fin(const float* __restrict__ sp, const float* __restrict__ biases,
      float* __restrict__ vout) {
    const int bc = blockIdx.x;
    const int b = bc >> 5, c = bc & 31;
    const int w = threadIdx.x >> 5, lane = threadIdx.x & 31;

    float s = 0.f;
    const float* p = sp + (size_t)b * NCH * KK + c * LL + lane;
#pragma unroll 8
    for (int n = w; n < NCH; n += 8) s += p[(size_t)n * KK];

    __shared__ float red[8][32];
    red[w][lane] = s;
    __syncthreads();

    if (w == 0) {
        float v = biases[c * LL + lane];
#pragma unroll
        for (int ww = 0; ww < 8; ww++) v += red[ww][lane];
        float n2 = v * v;
#pragma unroll
        for (int o = 16; o; o >>= 1) n2 += __shfl_xor_sync(0xffffffffu, n2, o);
        const float nn = sqrtf(n2);
        const float f = n2 / (1.0f + n2) / (nn + 1e-7f);   // squash factor
        vout[(size_t)b * KK + c * LL + lane] = f * v;
    }
}

extern "C" void kernel_launch(void* const* d_in, const int* in_sizes, int n_in,
                              void* d_out, int out_size) {
    const float* x      = (const float*)d_in[0];  // [32,8,8,32,32] = [B,N,iL]
    const float* Wt     = (const float*)d_in[1];  // [2048,32,1024]
    const float* biases = (const float*)d_in[2];  // [32,32]
    float* out = (float*)d_out;                   // [32,32,32]

    float *s0p, *sp, *v0, *v1, *dm;
    cudaGetSymbolAddress((void**)&s0p, g_s0p);
    cudaGetSymbolAddress((void**)&sp,  g_sp);
    cudaGetSymbolAddress((void**)&v0,  g_v0);
    cudaGetSymbolAddress((void**)&v1,  g_v1);
    cudaGetSymbolAddress((void**)&dm,  g_dummy);

    // 3 dummies keep k1 in the ncu-profiled slot.
    k_dummy<<<1, 32>>>(dm);                              // 0
    k_dummy<<<1, 32>>>(dm);                              // 1
    k_dummy<<<1, 32>>>(dm);                              // 2
    k1<<<dim3(NCH1, 4), 256>>>(x, Wt);                   // 3 <- profiled
    k_fin<NCH1><<<BB * CC, 256>>>(s0p, biases, v0);      // 4
    k_pass<1><<<dim3(PCH, BB), 256>>>(v0, v0, sp);       // 5
    k_fin<PCH><<<BB * CC, 256>>>(sp, biases, v1);        // 6
    k_pass<2><<<dim3(PCH, BB), 256>>>(v0, v1, sp);       // 7
    k_fin<PCH><<<BB * CC, 256>>>(sp, biases, out);       // 8
}

// round 11
// speedup vs baseline: 1.1991x; 1.0332x over previous
#include <cuda_runtime.h>
#include <cuda_fp16.h>

#define BB   32      // batch
#define NN   2048    // input capsules
#define IL   32      // input capsule length
#define CC   32      // output capsules
#define LL   32      // output capsule length
#define KK   1024    // CC*LL
#define NCH1 128     // j-chunks for u/s0 kernel (16 j each)
#define PCH  32      // pass CTAs per b (each CTA covers 64 j)

typedef unsigned long long ull;

// Scratch (device globals: allocation-free rule)
__device__ __half g_uh [(size_t)BB * NN * KK];    // 128 MB prediction tensor (fp16)
__device__ float  g_s0p[(size_t)BB * NCH1 * KK];  // s partials, round 0 (16 MB)
__device__ float  g_sp [(size_t)BB * PCH * KK];   // s partials, rounds 1/2 (4 MB)
__device__ float  g_v0 [BB * KK];
__device__ float  g_v1 [BB * KK];
__device__ float  g_dummy[1];

__device__ __forceinline__ void ffma2(ull& acc, ull a, ull b) {
    asm("fma.rn.f32x2 %0, %1, %2, %0;" : "+l"(acc) : "l"(a), "l"(b));
}
__device__ __forceinline__ void fadd2(ull& acc, ull a) {
    asm("add.rn.f32x2 %0, %1, %0;" : "+l"(acc) : "l"(a));
}
__device__ __forceinline__ float2 up2(ull v) {
    float2 f;
    asm("mov.b64 {%0, %1}, %2;" : "=f"(f.x), "=f"(f.y) : "l"(v));
    return f;
}
__device__ __forceinline__ ull splat(float v) {
    ull r;
    asm("mov.b64 %0, {%1, %1};" : "=l"(r) : "f"(v));
    return r;
}
__device__ __forceinline__ ull pack2(float a, float b) {
    ull r;
    asm("mov.b64 %0, {%1, %2};" : "=l"(r) : "f"(a), "f"(b));
    return r;
}
__device__ __forceinline__ __half2 geth2(const uint4& v, int p) {
    unsigned u = (&v.x)[p];
    return *reinterpret_cast<const __half2*>(&u);
}

__global__ void k_dummy(float* p) { if (threadIdx.x == 0) p[0] = 0.f; }

// K1 v8 = v5/v7 inner loop + WARP-PRIVATE W pipelines.
// Each warp owns a disjoint 32-k column slice (k = w*32 + kgl*4) and
// cp.asyncs ONLY its own 1 KB per stage -> stage consumption is guarded by
// per-warp wait_group + __syncwarp (~23 cyc) instead of CTA-wide
// __syncthreads. CTA barriers drop 64 -> 8 (x staging only); warps drift
// independently so one warp's DRAM hiccup no longer stalls the other 7.
// Thread: lane = bg*8 + kgl; owns 4 k x 8 b (4 f32x2 b-pairs). W read once
// chip-wide (disjoint slices). 5-stage ring, depth-4 prefetch.
__global__ void __launch_bounds__(256, 2)
k1(const float* __restrict__ x, const float* __restrict__ Wt) {
    const int w     = threadIdx.x >> 5;    // warp 0..7 -> k-slice [w*32, w*32+32)
    const int lane  = threadIdx.x & 31;
    const int kgl   = lane & 7;            // 4-k group within warp slice
    const int bg    = lane >> 3;           // 0..3 -> 8 b's
    const int chunk = blockIdx.x;          // 0..127
    const int kq    = blockIdx.y;          // 0..3
    const int j0g   = chunk * 16;

    __shared__ __align__(16) float wbuf[5][8][256];   // 40 KB W ring (warp-sliced)
    __shared__ __align__(16) float xs[2][32][36];     // 9 KB x (transposed, padded)

    // per-warp cp.async: lane covers row = lane>>2, 32 B at (lane&3)*8 floats
    const int cr = lane >> 2;
    const int cc = (lane & 3) * 8;

    auto issue_stage = [&](int g) {
        const int jg = j0g + (g >> 2);
        const int ibase = (g & 3) * 8;
        const float* src = Wt + (size_t)jg * (IL * KK) + (size_t)(ibase + cr) * KK
                         + kq * 256 + w * 32 + cc;
        unsigned dst = (unsigned)__cvta_generic_to_shared(&wbuf[g % 5][cr][w * 32 + cc]);
        asm volatile(
            "cp.async.cg.shared.global [%0], [%1], 16;\n\t"
            "cp.async.cg.shared.global [%2], [%3], 16;"
            :: "r"(dst), "l"(src), "r"(dst + 16), "l"(src + 4) : "memory");
    };

    ull acc[4][4], s0[4][4];               // [k][b-pair] f32x2
#pragma unroll
    for (int k = 0; k < 4; k++)
#pragma unroll
        for (int bp = 0; bp < 4; bp++) { acc[k][bp] = 0ull; s0[k][bp] = 0ull; }

    // prologue: 4 per-warp stages in flight
#pragma unroll
    for (int pg = 0; pg < 4; pg++) {
        issue_stage(pg);
        asm volatile("cp.async.commit_group;" ::: "memory");
    }

    for (int g = 0; g < 64; g++) {         // 64 stages: 16 j x 4 i-blocks of 8
        if ((g & 7) == 0) {
            // stage x for j-pair (transposed, pad 36 keeps rows 16B-aligned)
            __syncthreads();               // all warps done reading xs slots
            const int jp = j0g + (g >> 2);
#pragma unroll
            for (int r = 0; r < 8; r++) {
                int idx = threadIdx.x + 256 * r;
                int jl = idx >> 10, rem = idx & 1023;
                int b = rem >> 5, i = rem & 31;
                xs[jl][i][b] = x[((size_t)b * NN + jp + jl) * IL + i];
            }
            __syncthreads();
        }

        // wait for THIS warp's stage-g slice only
        asm volatile("cp.async.wait_group 3;" ::: "memory");
        __syncwarp();

        // compute stage g (8 i-rows)
        const int jl = (g >> 2) & 1;
        const int ib = (g & 3) * 8;
        const float (*wb)[256] = wbuf[g % 5];
#pragma unroll
        for (int ii = 0; ii < 8; ii++) {
            float4 wv = *reinterpret_cast<const float4*>(&wb[ii][w * 32 + kgl * 4]);
            ull ws0 = splat(wv.x), ws1 = splat(wv.y), ws2 = splat(wv.z), ws3 = splat(wv.w);
            float4 xa = *reinterpret_cast<const float4*>(&xs[jl][ib + ii][bg * 8]);
            float4 xb = *reinterpret_cast<const float4*>(&xs[jl][ib + ii][bg * 8 + 4]);
            ull xp0 = pack2(xa.x, xa.y), xp1 = pack2(xa.z, xa.w);
            ull xp2 = pack2(xb.x, xb.y), xp3 = pack2(xb.z, xb.w);
            ffma2(acc[0][0], ws0, xp0); ffma2(acc[0][1], ws0, xp1);
            ffma2(acc[0][2], ws0, xp2); ffma2(acc[0][3], ws0, xp3);
            ffma2(acc[1][0], ws1, xp0); ffma2(acc[1][1], ws1, xp1);
            ffma2(acc[1][2], ws1, xp2); ffma2(acc[1][3], ws1, xp3);
            ffma2(acc[2][0], ws2, xp0); ffma2(acc[2][1], ws2, xp1);
            ffma2(acc[2][2], ws2, xp2); ffma2(acc[2][3], ws2, xp3);
            ffma2(acc[3][0], ws3, xp0); ffma2(acc[3][1], ws3, xp1);
            ffma2(acc[3][2], ws3, xp2); ffma2(acc[3][3], ws3, xp3);
        }

        if ((g & 3) == 3) {
            // j complete: store u row (fp16), fold s0, reset acc
            const int jg = j0g + (g >> 2);
            const size_t kb = (size_t)kq * 256 + (size_t)(w * 32 + kgl * 4);
#pragma unroll
            for (int bp = 0; bp < 4; bp++) {
                float2 f0 = up2(acc[0][bp]), f1 = up2(acc[1][bp]);
                float2 f2 = up2(acc[2][bp]), f3 = up2(acc[3][bp]);
                const int be = bg * 8 + bp * 2;
                __half2 h0 = __floats2half2_rn(f0.x, f1.x);
                __half2 h1 = __floats2half2_rn(f2.x, f3.x);
                uint2 pk;
                pk.x = *reinterpret_cast<unsigned*>(&h0);
                pk.y = *reinterpret_cast<unsigned*>(&h1);
                *reinterpret_cast<uint2*>(g_uh + ((size_t)be * NN + jg) * KK + kb) = pk;
                h0 = __floats2half2_rn(f0.y, f1.y);
                h1 = __floats2half2_rn(f2.y, f3.y);
                pk.x = *reinterpret_cast<unsigned*>(&h0);
                pk.y = *reinterpret_cast<unsigned*>(&h1);
                *reinterpret_cast<uint2*>(g_uh + ((size_t)(be + 1) * NN + jg) * KK + kb) = pk;
#pragma unroll
                for (int k = 0; k < 4; k++) {
                    fadd2(s0[k][bp], acc[k][bp]);
                    acc[k][bp] = 0ull;
                }
            }
        }

        if (g + 4 < 64) issue_stage(g + 4);
        asm volatile("cp.async.commit_group;" ::: "memory");
    }

    // s0 partial store (softmax(0) coupling = 1/32)
    const float scl = 1.0f / 32.0f;
    const size_t kb = (size_t)kq * 256 + (size_t)(w * 32 + kgl * 4);
#pragma unroll
    for (int bp = 0; bp < 4; bp++) {
        float2 f0 = up2(s0[0][bp]), f1 = up2(s0[1][bp]);
        float2 f2 = up2(s0[2][bp]), f3 = up2(s0[3][bp]);
        const int be = bg * 8 + bp * 2;
        *reinterpret_cast<float4*>(g_s0p + ((size_t)be * NCH1 + chunk) * KK + kb) =
            make_float4(f0.x * scl, f1.x * scl, f2.x * scl, f3.x * scl);
        *reinterpret_cast<float4*>(g_s0p + ((size_t)(be + 1) * NCH1 + chunk) * KK + kb) =
            make_float4(f0.y * scl, f1.y * scl, f2.y * scl, f3.y * scl);
    }
}

// Routing pass v4 (measured ~28us each). Lane t's uint4 group q (index
// t+32q of the u row) covers k = 8t+256q+e (e<8), all in capsule
// c_q = (t>>2)+8q. Quad shfl completes each logit; shfl xor 4/8/16 spans
// the 32 capsules for the softmax. v as fp16x2 registers; u raw, converted
// on the fly. Two rows per body, interleaved softmax chains.
template <int NP>
__global__ void __launch_bounds__(256, 2)
k_pass(const float* __restrict__ vin0, const float* __restrict__ vin1,
       float* __restrict__ sp) {
    const int b = blockIdx.y;
    const int w = threadIdx.x >> 5;
    const int t = threadIdx.x & 31;

    __shared__ float red[8][1032];     // CTA reduction (16B-aligned rows)

    // v as half2 registers at the u k-mapping (NP==2 folds v0+v1)
    __half2 vh[16];
#pragma unroll
    for (int q = 0; q < 4; q++) {
        float4 a = *reinterpret_cast<const float4*>(vin0 + (size_t)b * KK + 8 * t + 256 * q);
        float4 c4 = *reinterpret_cast<const float4*>(vin0 + (size_t)b * KK + 8 * t + 256 * q + 4);
        if (NP == 2) {
            float4 a1 = *reinterpret_cast<const float4*>(vin1 + (size_t)b * KK + 8 * t + 256 * q);
            float4 c1 = *reinterpret_cast<const float4*>(vin1 + (size_t)b * KK + 8 * t + 256 * q + 4);
            a.x += a1.x; a.y += a1.y; a.z += a1.z; a.w += a1.w;
            c4.x += c1.x; c4.y += c1.y; c4.z += c1.z; c4.w += c1.w;
        }
        vh[q * 4 + 0] = __floats2half2_rn(a.x, a.y);
        vh[q * 4 + 1] = __floats2half2_rn(a.z, a.w);
        vh[q * 4 + 2] = __floats2half2_rn(c4.x, c4.y);
        vh[q * 4 + 3] = __floats2half2_rn(c4.z, c4.w);
    }

    float sacc[32];
#pragma unroll
    for (int l = 0; l < 32; l++) sacc[l] = 0.f;

    const int jbase = blockIdx.x * 64 + w * 8;   // 8 warps x 8 j = 64 j / CTA
    const uint4* up = reinterpret_cast<const uint4*>(g_uh + ((size_t)b * NN + jbase) * KK);

    uint4 raw0[4], raw1[4];
#pragma unroll
    for (int q = 0; q < 4; q++) raw0[q] = up[q * 32 + t];          // j0
#pragma unroll
    for (int q = 0; q < 4; q++) raw1[q] = up[128 + q * 32 + t];    // j1

    for (int jb = 0; jb < 8; jb += 2) {
        // free raw0 early: copy, then prefetch j+2 into it
        uint4 cpy0[4];
#pragma unroll
        for (int q = 0; q < 4; q++) cpy0[q] = raw0[q];
        if (jb + 2 < 8) {
#pragma unroll
            for (int q = 0; q < 4; q++) raw0[q] = up[(jb + 2) * 128 + q * 32 + t];
        }

        // logits for both rows (HFMA2 dot), interleaved
        float d0[4], d1[4];
#pragma unroll
        for (int q = 0; q < 4; q++) {
            __half2 a0 = __float2half2_rn(0.f), a1 = __float2half2_rn(0.f);
#pragma unroll
            for (int p = 0; p < 4; p++) {
                a0 = __hfma2(geth2(cpy0[q], p), vh[q * 4 + p], a0);
                a1 = __hfma2(geth2(raw1[q], p), vh[q * 4 + p], a1);
            }
            float2 f0 = __half22float2(a0), f1 = __half22float2(a1);
            d0[q] = f0.x + f0.y;
            d1[q] = f1.x + f1.y;
            d0[q] += __shfl_xor_sync(0xffffffffu, d0[q], 1);
            d1[q] += __shfl_xor_sync(0xffffffffu, d1[q], 1);
            d0[q] += __shfl_xor_sync(0xffffffffu, d0[q], 2);
            d1[q] += __shfl_xor_sync(0xffffffffu, d1[q], 2);
        }

        // softmax over 32 capsules, two independent chains interleaved
        float m0 = fmaxf(fmaxf(d0[0], d0[1]), fmaxf(d0[2], d0[3]));
        float m1 = fmaxf(fmaxf(d1[0], d1[1]), fmaxf(d1[2], d1[3]));
        m0 = fmaxf(m0, __shfl_xor_sync(0xffffffffu, m0, 4));
        m1 = fmaxf(m1, __shfl_xor_sync(0xffffffffu, m1, 4));
        m0 = fmaxf(m0, __shfl_xor_sync(0xffffffffu, m0, 8));
        m1 = fmaxf(m1, __shfl_xor_sync(0xffffffffu, m1, 8));
        m0 = fmaxf(m0, __shfl_xor_sync(0xffffffffu, m0, 16));
        m1 = fmaxf(m1, __shfl_xor_sync(0xffffffffu, m1, 16));

        float ce0[4], ce1[4];
#pragma unroll
        for (int q = 0; q < 4; q++) {
            ce0[q] = __expf(d0[q] - m0);
            ce1[q] = __expf(d1[q] - m1);
        }
        float Z0 = (ce0[0] + ce0[1]) + (ce0[2] + ce0[3]);
        float Z1 = (ce1[0] + ce1[1]) + (ce1[2] + ce1[3]);
        Z0 += __shfl_xor_sync(0xffffffffu, Z0, 4);
        Z1 += __shfl_xor_sync(0xffffffffu, Z1, 4);
        Z0 += __shfl_xor_sync(0xffffffffu, Z0, 8);
        Z1 += __shfl_xor_sync(0xffffffffu, Z1, 8);
        Z0 += __shfl_xor_sync(0xffffffffu, Z0, 16);
        Z1 += __shfl_xor_sync(0xffffffffu, Z1, 16);
        const float i0 = __fdividef(1.0f, Z0);
        const float i1 = __fdividef(1.0f, Z1);

        // accumulate both rows (cvt on the fly)
#pragma unroll
        for (int q = 0; q < 4; q++) {
            const float c0 = ce0[q] * i0;
            const float c1 = ce1[q] * i1;
#pragma unroll
            for (int p = 0; p < 4; p++) {
                float2 f = __half22float2(geth2(cpy0[q], p));
                sacc[8 * q + 2 * p]     += c0 * f.x;
                sacc[8 * q + 2 * p + 1] += c0 * f.y;
                f = __half22float2(geth2(raw1[q], p));
                sacc[8 * q + 2 * p]     += c1 * f.x;
                sacc[8 * q + 2 * p + 1] += c1 * f.y;
            }
        }

        // raw1 now free: prefetch j+3
        if (jb + 3 < 8) {
#pragma unroll
            for (int q = 0; q < 4; q++) raw1[q] = up[(jb + 3) * 128 + q * 32 + t];
        }
    }

    // CTA reduction across the 8 warps (natural k layout)
#pragma unroll
    for (int q = 0; q < 4; q++) {
        *reinterpret_cast<float4*>(&red[w][8 * t + 256 * q])     =
            make_float4(sacc[8 * q + 0], sacc[8 * q + 1], sacc[8 * q + 2], sacc[8 * q + 3]);
        *reinterpret_cast<float4*>(&red[w][8 * t + 256 * q + 4]) =
            make_float4(sacc[8 * q + 4], sacc[8 * q + 5], sacc[8 * q + 6], sacc[8 * q + 7]);
    }
    __syncthreads();

    float4 s = make_float4(0.f, 0.f, 0.f, 0.f);
#pragma unroll
    for (int ww = 0; ww < 8; ww++) {
        float4 p = *reinterpret_cast<const float4*>(&red[ww][4 * threadIdx.x]);
        s.x += p.x; s.y += p.y; s.z += p.z; s.w += p.w;
    }
    *reinterpret_cast<float4*>(sp + ((size_t)b * PCH + blockIdx.x) * KK + 4 * threadIdx.x) = s;
}

// Finalize: reduce NCH chunk partials + biases, squash -> v.
// One CTA (8 warps) per (b,c) for memory-level parallelism on the reduction.
template <int NCH>
__global__ void __launch_bounds__(256)
k_fin(const float* __restrict__ sp, const float* __restrict__ biases,
      float* __restrict__ vout) {
    const int bc = blockIdx.x;
    const int b = bc >> 5, c = bc & 31;
    const int w = threadIdx.x >> 5, lane = threadIdx.x & 31;

    float s = 0.f;
    const float* p = sp + (size_t)b * NCH * KK + c * LL + lane;
#pragma unroll 8
    for (int n = w; n < NCH; n += 8) s += p[(size_t)n * KK];

    __shared__ float red[8][32];
    red[w][lane] = s;
    __syncthreads();

    if (w == 0) {
        float v = biases[c * LL + lane];
#pragma unroll
        for (int ww = 0; ww < 8; ww++) v += red[ww][lane];
        float n2 = v * v;
#pragma unroll
        for (int o = 16; o; o >>= 1) n2 += __shfl_xor_sync(0xffffffffu, n2, o);
        const float nn = sqrtf(n2);
        const float f = n2 / (1.0f + n2) / (nn + 1e-7f);   // squash factor
        vout[(size_t)b * KK + c * LL + lane] = f * v;
    }
}

extern "C" void kernel_launch(void* const* d_in, const int* in_sizes, int n_in,
                              void* d_out, int out_size) {
    const float* x      = (const float*)d_in[0];  // [32,8,8,32,32] = [B,N,iL]
    const float* Wt     = (const float*)d_in[1];  // [2048,32,1024]
    const float* biases = (const float*)d_in[2];  // [32,32]
    float* out = (float*)d_out;                   // [32,32,32]

    float *s0p, *sp, *v0, *v1, *dm;
    cudaGetSymbolAddress((void**)&s0p, g_s0p);
    cudaGetSymbolAddress((void**)&sp,  g_sp);
    cudaGetSymbolAddress((void**)&v0,  g_v0);
    cudaGetSymbolAddress((void**)&v1,  g_v1);
    cudaGetSymbolAddress((void**)&dm,  g_dummy);

    // 3 dummies keep k1 in the ncu-profiled slot.
    k_dummy<<<1, 32>>>(dm);                              // 0
    k_dummy<<<1, 32>>>(dm);                              // 1
    k_dummy<<<1, 32>>>(dm);                              // 2
    k1<<<dim3(NCH1, 4), 256>>>(x, Wt);                   // 3 <- profiled
    k_fin<NCH1><<<BB * CC, 256>>>(s0p, biases, v0);      // 4
    k_pass<1><<<dim3(PCH, BB), 256>>>(v0, v0, sp);       // 5
    k_fin<PCH><<<BB * CC, 256>>>(sp, biases, v1);        // 6
    k_pass<2><<<dim3(PCH, BB), 256>>>(v0, v1, sp);       // 7
    k_fin<PCH><<<BB * CC, 256>>>(sp, biases, out);       // 8
}

// round 12
// speedup vs baseline: 1.2838x; 1.0706x over previous
#include <cuda_runtime.h>
#include <cuda_fp16.h>

#define BB   32      // batch
#define NN   2048    // input capsules
#define IL   32      // input capsule length
#define CC   32      // output capsules
#define LL   32      // output capsule length
#define KK   1024    // CC*LL
#define NCH1 148     // j-chunks for k1 (13-14 j each; 148x4 = 592 CTAs = 2 FULL waves)
#define PCH  32      // pass CTAs per b (each CTA covers 64 j)

typedef unsigned long long ull;

// Scratch (device globals: allocation-free rule)
__device__ __half g_uh [(size_t)BB * NN * KK];    // 128 MB prediction tensor (fp16)
__device__ float  g_s0p[(size_t)BB * NCH1 * KK];  // s partials, round 0 (19 MB)
__device__ float  g_sp [(size_t)BB * PCH * KK];   // s partials, rounds 1/2 (4 MB)
__device__ float  g_v0 [BB * KK];
__device__ float  g_v1 [BB * KK];
__device__ float  g_dummy[1];

__device__ __forceinline__ void ffma2(ull& acc, ull a, ull b) {
    asm("fma.rn.f32x2 %0, %1, %2, %0;" : "+l"(acc) : "l"(a), "l"(b));
}
__device__ __forceinline__ void fadd2(ull& acc, ull a) {
    asm("add.rn.f32x2 %0, %1, %0;" : "+l"(acc) : "l"(a));
}
__device__ __forceinline__ float2 up2(ull v) {
    float2 f;
    asm("mov.b64 {%0, %1}, %2;" : "=f"(f.x), "=f"(f.y) : "l"(v));
    return f;
}
__device__ __forceinline__ ull splat(float v) {
    ull r;
    asm("mov.b64 %0, {%1, %1};" : "=l"(r) : "f"(v));
    return r;
}
__device__ __forceinline__ ull pack2(float a, float b) {
    ull r;
    asm("mov.b64 %0, {%1, %2};" : "=l"(r) : "f"(a), "f"(b));
    return r;
}
__device__ __forceinline__ __half2 geth2(const uint4& v, int p) {
    unsigned u = (&v.x)[p];
    return *reinterpret_cast<const __half2*>(&u);
}

__global__ void k_dummy(float* p) { if (threadIdx.x == 0) p[0] = 0.f; }

// K1 v9 = v8 (warp-private cp.async W pipelines) + exact-wave grid + L2 hints.
// grid (148,4) = 592 CTAs = exactly 2 full waves at 2 CTAs/SM -> no idle
// tail (v8's 1.73-wave grid wasted ~15us). Chunks carry 13-14 j (dynamic
// stage count). W cp.asyncs are tagged L2::evict_first: W is read-once, so
// keeping it out of LRU lets the dirty u tensor (128 MB ~ L2 capacity)
// survive in L2 for the routing passes.
__global__ void __launch_bounds__(256, 2)
k1(const float* __restrict__ x, const float* __restrict__ Wt) {
    const int w     = threadIdx.x >> 5;    // warp 0..7 -> k-slice [w*32, w*32+32)
    const int lane  = threadIdx.x & 31;
    const int kgl   = lane & 7;            // 4-k group within warp slice
    const int bg    = lane >> 3;           // 0..3 -> 8 b's
    const int chunk = blockIdx.x;          // 0..147
    const int kq    = blockIdx.y;          // 0..3
    const int j0    = (chunk * NN) / NCH1;
    const int j1    = ((chunk + 1) * NN) / NCH1;
    const int nst   = 4 * (j1 - j0);       // 52 or 56 stages

    __shared__ __align__(16) float wbuf[5][8][256];   // 40 KB W ring (warp-sliced)
    __shared__ __align__(16) float xs[2][32][36];     // 9 KB x (transposed, padded)

    // per-warp cp.async: lane covers row = lane>>2, 32 B at (lane&3)*8 floats
    const int cr = lane >> 2;
    const int cc = (lane & 3) * 8;

    ull pol;   // read-once W: evict-first so u stays resident in L2
    asm("createpolicy.fractional.L2::evict_first.b64 %0, 1.0;" : "=l"(pol));

    auto issue_stage = [&](int g) {
        const int jg = j0 + (g >> 2);
        const int ibase = (g & 3) * 8;
        const float* src = Wt + (size_t)jg * (IL * KK) + (size_t)(ibase + cr) * KK
                         + kq * 256 + w * 32 + cc;
        unsigned dst = (unsigned)__cvta_generic_to_shared(&wbuf[g % 5][cr][w * 32 + cc]);
        asm volatile(
            "cp.async.cg.shared.global.L2::cache_hint [%0], [%1], 16, %2;\n\t"
            "cp.async.cg.shared.global.L2::cache_hint [%3], [%4], 16, %2;"
            :: "r"(dst), "l"(src), "l"(pol), "r"(dst + 16), "l"(src + 4) : "memory");
    };

    ull acc[4][4], s0[4][4];               // [k][b-pair] f32x2
#pragma unroll
    for (int k = 0; k < 4; k++)
#pragma unroll
        for (int bp = 0; bp < 4; bp++) { acc[k][bp] = 0ull; s0[k][bp] = 0ull; }

    // prologue: 4 per-warp stages in flight (nst >= 52, always valid)
#pragma unroll
    for (int pg = 0; pg < 4; pg++) {
        issue_stage(pg);
        asm volatile("cp.async.commit_group;" ::: "memory");
    }

    for (int g = 0; g < nst; g++) {        // stages: j-count x 4 i-blocks of 8
        if ((g & 7) == 0) {
            // stage x for j-pair (transposed, pad 36 keeps rows 16B-aligned)
            __syncthreads();               // all warps done reading xs slots
            const int jp = j0 + (g >> 2);
#pragma unroll
            for (int r = 0; r < 8; r++) {
                int idx = threadIdx.x + 256 * r;
                int jl = idx >> 10, rem = idx & 1023;
                int b = rem >> 5, i = rem & 31;
                int jj = jp + jl; if (jj > NN - 1) jj = NN - 1;   // clamp (tail pair)
                xs[jl][i][b] = x[((size_t)b * NN + jj) * IL + i];
            }
            __syncthreads();
        }

        // wait for THIS warp's stage-g slice only
        asm volatile("cp.async.wait_group 3;" ::: "memory");
        __syncwarp();

        // compute stage g (8 i-rows)
        const int jl = (g >> 2) & 1;
        const int ib = (g & 3) * 8;
        const float (*wb)[256] = wbuf[g % 5];
#pragma unroll
        for (int ii = 0; ii < 8; ii++) {
            float4 wv = *reinterpret_cast<const float4*>(&wb[ii][w * 32 + kgl * 4]);
            ull ws0 = splat(wv.x), ws1 = splat(wv.y), ws2 = splat(wv.z), ws3 = splat(wv.w);
            float4 xa = *reinterpret_cast<const float4*>(&xs[jl][ib + ii][bg * 8]);
            float4 xb = *reinterpret_cast<const float4*>(&xs[jl][ib + ii][bg * 8 + 4]);
            ull xp0 = pack2(xa.x, xa.y), xp1 = pack2(xa.z, xa.w);
            ull xp2 = pack2(xb.x, xb.y), xp3 = pack2(xb.z, xb.w);
            ffma2(acc[0][0], ws0, xp0); ffma2(acc[0][1], ws0, xp1);
            ffma2(acc[0][2], ws0, xp2); ffma2(acc[0][3], ws0, xp3);
            ffma2(acc[1][0], ws1, xp0); ffma2(acc[1][1], ws1, xp1);
            ffma2(acc[1][2], ws1, xp2); ffma2(acc[1][3], ws1, xp3);
            ffma2(acc[2][0], ws2, xp0); ffma2(acc[2][1], ws2, xp1);
            ffma2(acc[2][2], ws2, xp2); ffma2(acc[2][3], ws2, xp3);
            ffma2(acc[3][0], ws3, xp0); ffma2(acc[3][1], ws3, xp1);
            ffma2(acc[3][2], ws3, xp2); ffma2(acc[3][3], ws3, xp3);
        }

        if ((g & 3) == 3) {
            // j complete: store u row (fp16), fold s0, reset acc
            const int jg = j0 + (g >> 2);
            const size_t kb = (size_t)kq * 256 + (size_t)(w * 32 + kgl * 4);
#pragma unroll
            for (int bp = 0; bp < 4; bp++) {
                float2 f0 = up2(acc[0][bp]), f1 = up2(acc[1][bp]);
                float2 f2 = up2(acc[2][bp]), f3 = up2(acc[3][bp]);
                const int be = bg * 8 + bp * 2;
                __half2 h0 = __floats2half2_rn(f0.x, f1.x);
                __half2 h1 = __floats2half2_rn(f2.x, f3.x);
                uint2 pk;
                pk.x = *reinterpret_cast<unsigned*>(&h0);
                pk.y = *reinterpret_cast<unsigned*>(&h1);
                *reinterpret_cast<uint2*>(g_uh + ((size_t)be * NN + jg) * KK + kb) = pk;
                h0 = __floats2half2_rn(f0.y, f1.y);
                h1 = __floats2half2_rn(f2.y, f3.y);
                pk.x = *reinterpret_cast<unsigned*>(&h0);
                pk.y = *reinterpret_cast<unsigned*>(&h1);
                *reinterpret_cast<uint2*>(g_uh + ((size_t)(be + 1) * NN + jg) * KK + kb) = pk;
#pragma unroll
                for (int k = 0; k < 4; k++) {
                    fadd2(s0[k][bp], acc[k][bp]);
                    acc[k][bp] = 0ull;
                }
            }
        }

        if (g + 4 < nst) issue_stage(g + 4);
        asm volatile("cp.async.commit_group;" ::: "memory");
    }

    // s0 partial store (softmax(0) coupling = 1/32)
    const float scl = 1.0f / 32.0f;
    const size_t kb = (size_t)kq * 256 + (size_t)(w * 32 + kgl * 4);
#pragma unroll
    for (int bp = 0; bp < 4; bp++) {
        float2 f0 = up2(s0[0][bp]), f1 = up2(s0[1][bp]);
        float2 f2 = up2(s0[2][bp]), f3 = up2(s0[3][bp]);
        const int be = bg * 8 + bp * 2;
        *reinterpret_cast<float4*>(g_s0p + ((size_t)be * NCH1 + chunk) * KK + kb) =
            make_float4(f0.x * scl, f1.x * scl, f2.x * scl, f3.x * scl);
        *reinterpret_cast<float4*>(g_s0p + ((size_t)(be + 1) * NCH1 + chunk) * KK + kb) =
            make_float4(f0.y * scl, f1.y * scl, f2.y * scl, f3.y * scl);
    }
}

// Routing pass v4 (measured ~28us each; should now hit u in L2). Lane t's
// uint4 group q (index t+32q of the u row) covers k = 8t+256q+e (e<8), all
// in capsule c_q = (t>>2)+8q. Quad shfl completes each logit; shfl xor
// 4/8/16 spans the 32 capsules for the softmax. v as fp16x2 registers;
// u raw, converted on the fly. Two rows per body, interleaved chains.
template <int NP>
__global__ void __launch_bounds__(256, 2)
k_pass(const float* __restrict__ vin0, const float* __restrict__ vin1,
       float* __restrict__ sp) {
    const int b = blockIdx.y;
    const int w = threadIdx.x >> 5;
    const int t = threadIdx.x & 31;

    __shared__ float red[8][1032];     // CTA reduction (16B-aligned rows)

    // v as half2 registers at the u k-mapping (NP==2 folds v0+v1)
    __half2 vh[16];
#pragma unroll
    for (int q = 0; q < 4; q++) {
        float4 a = *reinterpret_cast<const float4*>(vin0 + (size_t)b * KK + 8 * t + 256 * q);
        float4 c4 = *reinterpret_cast<const float4*>(vin0 + (size_t)b * KK + 8 * t + 256 * q + 4);
        if (NP == 2) {
            float4 a1 = *reinterpret_cast<const float4*>(vin1 + (size_t)b * KK + 8 * t + 256 * q);
            float4 c1 = *reinterpret_cast<const float4*>(vin1 + (size_t)b * KK + 8 * t + 256 * q + 4);
            a.x += a1.x; a.y += a1.y; a.z += a1.z; a.w += a1.w;
            c4.x += c1.x; c4.y += c1.y; c4.z += c1.z; c4.w += c1.w;
        }
        vh[q * 4 + 0] = __floats2half2_rn(a.x, a.y);
        vh[q * 4 + 1] = __floats2half2_rn(a.z, a.w);
        vh[q * 4 + 2] = __floats2half2_rn(c4.x, c4.y);
        vh[q * 4 + 3] = __floats2half2_rn(c4.z, c4.w);
    }

    float sacc[32];
#pragma unroll
    for (int l = 0; l < 32; l++) sacc[l] = 0.f;

    const int jbase = blockIdx.x * 64 + w * 8;   // 8 warps x 8 j = 64 j / CTA
    const uint4* up = reinterpret_cast<const uint4*>(g_uh + ((size_t)b * NN + jbase) * KK);

    uint4 raw0[4], raw1[4];
#pragma unroll
    for (int q = 0; q < 4; q++) raw0[q] = up[q * 32 + t];          // j0
#pragma unroll
    for (int q = 0; q < 4; q++) raw1[q] = up[128 + q * 32 + t];    // j1

    for (int jb = 0; jb < 8; jb += 2) {
        // free raw0 early: copy, then prefetch j+2 into it
        uint4 cpy0[4];
#pragma unroll
        for (int q = 0; q < 4; q++) cpy0[q] = raw0[q];
        if (jb + 2 < 8) {
#pragma unroll
            for (int q = 0; q < 4; q++) raw0[q] = up[(jb + 2) * 128 + q * 32 + t];
        }

        // logits for both rows (HFMA2 dot), interleaved
        float d0[4], d1[4];
#pragma unroll
        for (int q = 0; q < 4; q++) {
            __half2 a0 = __float2half2_rn(0.f), a1 = __float2half2_rn(0.f);
#pragma unroll
            for (int p = 0; p < 4; p++) {
                a0 = __hfma2(geth2(cpy0[q], p), vh[q * 4 + p], a0);
                a1 = __hfma2(geth2(raw1[q], p), vh[q * 4 + p], a1);
            }
            float2 f0 = __half22float2(a0), f1 = __half22float2(a1);
            d0[q] = f0.x + f0.y;
            d1[q] = f1.x + f1.y;
            d0[q] += __shfl_xor_sync(0xffffffffu, d0[q], 1);
            d1[q] += __shfl_xor_sync(0xffffffffu, d1[q], 1);
            d0[q] += __shfl_xor_sync(0xffffffffu, d0[q], 2);
            d1[q] += __shfl_xor_sync(0xffffffffu, d1[q], 2);
        }

        // softmax over 32 capsules, two independent chains interleaved
        float m0 = fmaxf(fmaxf(d0[0], d0[1]), fmaxf(d0[2], d0[3]));
        float m1 = fmaxf(fmaxf(d1[0], d1[1]), fmaxf(d1[2], d1[3]));
        m0 = fmaxf(m0, __shfl_xor_sync(0xffffffffu, m0, 4));
        m1 = fmaxf(m1, __shfl_xor_sync(0xffffffffu, m1, 4));
        m0 = fmaxf(m0, __shfl_xor_sync(0xffffffffu, m0, 8));
        m1 = fmaxf(m1, __shfl_xor_sync(0xffffffffu, m1, 8));
        m0 = fmaxf(m0, __shfl_xor_sync(0xffffffffu, m0, 16));
        m1 = fmaxf(m1, __shfl_xor_sync(0xffffffffu, m1, 16));

        float ce0[4], ce1[4];
#pragma unroll
        for (int q = 0; q < 4; q++) {
            ce0[q] = __expf(d0[q] - m0);
            ce1[q] = __expf(d1[q] - m1);
        }
        float Z0 = (ce0[0] + ce0[1]) + (ce0[2] + ce0[3]);
        float Z1 = (ce1[0] + ce1[1]) + (ce1[2] + ce1[3]);
        Z0 += __shfl_xor_sync(0xffffffffu, Z0, 4);
        Z1 += __shfl_xor_sync(0xffffffffu, Z1, 4);
        Z0 += __shfl_xor_sync(0xffffffffu, Z0, 8);
        Z1 += __shfl_xor_sync(0xffffffffu, Z1, 8);
        Z0 += __shfl_xor_sync(0xffffffffu, Z0, 16);
        Z1 += __shfl_xor_sync(0xffffffffu, Z1, 16);
        const float i0 = __fdividef(1.0f, Z0);
        const float i1 = __fdividef(1.0f, Z1);

        // accumulate both rows (cvt on the fly)
#pragma unroll
        for (int q = 0; q < 4; q++) {
            const float c0 = ce0[q] * i0;
            const float c1 = ce1[q] * i1;
#pragma unroll
            for (int p = 0; p < 4; p++) {
                float2 f = __half22float2(geth2(cpy0[q], p));
                sacc[8 * q + 2 * p]     += c0 * f.x;
                sacc[8 * q + 2 * p + 1] += c0 * f.y;
                f = __half22float2(geth2(raw1[q], p));
                sacc[8 * q + 2 * p]     += c1 * f.x;
                sacc[8 * q + 2 * p + 1] += c1 * f.y;
            }
        }

        // raw1 now free: prefetch j+3
        if (jb + 3 < 8) {
#pragma unroll
            for (int q = 0; q < 4; q++) raw1[q] = up[(jb + 3) * 128 + q * 32 + t];
        }
    }

    // CTA reduction across the 8 warps (natural k layout)
#pragma unroll
    for (int q = 0; q < 4; q++) {
        *reinterpret_cast<float4*>(&red[w][8 * t + 256 * q])     =
            make_float4(sacc[8 * q + 0], sacc[8 * q + 1], sacc[8 * q + 2], sacc[8 * q + 3]);
        *reinterpret_cast<float4*>(&red[w][8 * t + 256 * q + 4]) =
            make_float4(sacc[8 * q + 4], sacc[8 * q + 5], sacc[8 * q + 6], sacc[8 * q + 7]);
    }
    __syncthreads();

    float4 s = make_float4(0.f, 0.f, 0.f, 0.f);
#pragma unroll
    for (int ww = 0; ww < 8; ww++) {
        float4 p = *reinterpret_cast<const float4*>(&red[ww][4 * threadIdx.x]);
        s.x += p.x; s.y += p.y; s.z += p.z; s.w += p.w;
    }
    *reinterpret_cast<float4*>(sp + ((size_t)b * PCH + blockIdx.x) * KK + 4 * threadIdx.x) = s;
}

// Finalize: reduce NCH chunk partials + biases, squash -> v.
// One CTA (8 warps) per (b,c) for memory-level parallelism on the reduction.
template <int NCH>
__global__ void __launch_bounds__(256)
k_fin(const float* __restrict__ sp, const float* __restrict__ biases,
      float* __restrict__ vout) {
    const int bc = blockIdx.x;
    const int b = bc >> 5, c = bc & 31;
    const int w = threadIdx.x >> 5, lane = threadIdx.x & 31;

    float s = 0.f;
    const float* p = sp + (size_t)b * NCH * KK + c * LL + lane;
#pragma unroll 8
    for (int n = w; n < NCH; n += 8) s += p[(size_t)n * KK];

    __shared__ float red[8][32];
    red[w][lane] = s;
    __syncthreads();

    if (w == 0) {
        float v = biases[c * LL + lane];
#pragma unroll
        for (int ww = 0; ww < 8; ww++) v += red[ww][lane];
        float n2 = v * v;
#pragma unroll
        for (int o = 16; o; o >>= 1) n2 += __shfl_xor_sync(0xffffffffu, n2, o);
        const float nn = sqrtf(n2);
        const float f = n2 / (1.0f + n2) / (nn + 1e-7f);   // squash factor
        vout[(size_t)b * KK + c * LL + lane] = f * v;
    }
}

extern "C" void kernel_launch(void* const* d_in, const int* in_sizes, int n_in,
                              void* d_out, int out_size) {
    const float* x      = (const float*)d_in[0];  // [32,8,8,32,32] = [B,N,iL]
    const float* Wt     = (const float*)d_in[1];  // [2048,32,1024]
    const float* biases = (const float*)d_in[2];  // [32,32]
    float* out = (float*)d_out;                   // [32,32,32]

    float *s0p, *sp, *v0, *v1, *dm;
    cudaGetSymbolAddress((void**)&s0p, g_s0p);
    cudaGetSymbolAddress((void**)&sp,  g_sp);
    cudaGetSymbolAddress((void**)&v0,  g_v0);
    cudaGetSymbolAddress((void**)&v1,  g_v1);
    cudaGetSymbolAddress((void**)&dm,  g_dummy);

    // 3 dummies keep k1 in the ncu-profiled slot.
    k_dummy<<<1, 32>>>(dm);                              // 0
    k_dummy<<<1, 32>>>(dm);                              // 1
    k_dummy<<<1, 32>>>(dm);                              // 2
    k1<<<dim3(NCH1, 4), 256>>>(x, Wt);                   // 3 <- profiled
    k_fin<NCH1><<<BB * CC, 256>>>(s0p, biases, v0);      // 4
    k_pass<1><<<dim3(PCH, BB), 256>>>(v0, v0, sp);       // 5
    k_fin<PCH><<<BB * CC, 256>>>(sp, biases, v1);        // 6
    k_pass<2><<<dim3(PCH, BB), 256>>>(v0, v1, sp);       // 7
    k_fin<PCH><<<BB * CC, 256>>>(sp, biases, out);       // 8
}